// round 15
// baseline (speedup 1.0000x reference)
#include <cuda_runtime.h>
#include <cuda_fp16.h>
#include <cstdint>

#define Bc 2
#define Nv 9
#define CBc 80
#define Hh 120
#define Ww 160
#define Dd 64
#define Pp 80000
#define HW (Hh*Ww)            // 19200
#define MTOT (Bc*Nv*HW)       // 345600

#define KM_TILES   (MTOT/128)        // 2700 tiles of 128 px
#define KM_PERSIST 300               // persistent keymap blocks (~1 wave)
#define QG_BLOCKS  (Pp/128)          // 625
#define CP_BLOCKS  ((Pp + 255)/256)  // 313
#define AT_BLOCKS  ((Pp + 31)/32)    // 2500

// Interleaved fp16 key maps: record = 64 half2 words per pixel (256 B).
// word 2j   = {KM1[2j], KM1[2j+1]},  word 2j+1 = {KM2[2j], KM2[2j+1]}
__device__ __half2 g_KMIh[(size_t)MTOT*64];
__device__ float   g_Q[(size_t)Pp*128];    // [p][0:64]=q1, [p][64:128]=q2v
__device__ int     g_selcnt;
__device__ int     g_selidx[Pp];

// smem byte layout for keymap path
#define BH_BYTES   (128*176)          // Bh[128 d][88 halfs] (80 used + pad)
#define AH_BYTES   (128*48)           // one A buffer: [128 px][24 halfs] (16 used)
#define KM_SMEM    (BH_BYTES + 2*AH_BYTES + 512)   // 35328
#define QG_SMEM    ((64*132 + 8*132 + 128)*4)      // 38528

__device__ __forceinline__ uint32_t h2u(__half2 h) {
    return *(uint32_t*)&h;
}

__device__ __forceinline__ float frcp(float x) {
    float r;
    asm("rcp.approx.f32 %0, %1;" : "=f"(r) : "f"(x));
    return r;
}

__device__ __forceinline__ void mma_f16(float* c,
                                        uint32_t a0, uint32_t a1,
                                        uint32_t a2, uint32_t a3,
                                        uint32_t b0, uint32_t b1) {
    asm volatile(
        "mma.sync.aligned.m16n8k16.row.col.f32.f16.f16.f32 "
        "{%0,%1,%2,%3},{%4,%5,%6,%7},{%8,%9},{%0,%1,%2,%3};"
        : "+f"(c[0]), "+f"(c[1]), "+f"(c[2]), "+f"(c[3])
        : "r"(a0), "r"(a1), "r"(a2), "r"(a3), "r"(b0), "r"(b1));
}

// ---------------------------------------------------------------------------
// Merged kernel 1:
//   blocks [0, KM_PERSIST)  : PERSISTENT key_maps (fp16 MMA, weights loaded once,
//                             9 tiles per block)
//   blocks [KMP, KMP+QG)    : q-GEMM (fp32 cores)
//   blocks [KMP+QG, +CP)    : compaction (sel list + passthrough rows)
// ---------------------------------------------------------------------------
__global__ __launch_bounds__(256) void keymap_qgemm_kernel(
    const float* __restrict__ img,
    const float* __restrict__ Wk1, const float* __restrict__ bk1,
    const float* __restrict__ Wk2, const float* __restrict__ bk2,
    const float* __restrict__ vox,
    const float* __restrict__ Wq1, const float* __restrict__ bq1,
    const float* __restrict__ Wq2, const float* __restrict__ bq2,
    const int*   __restrict__ cmask,
    float* __restrict__ out)
{
    extern __shared__ __align__(16) float dyn[];
    int tid = threadIdx.x;

    if (blockIdx.x < KM_PERSIST) {
        // ================= keymap: persistent fp16 MMA path =================
        char*  smem    = (char*)dyn;
        char*  BhB     = smem;                      // halfs, row stride 176 B
        char*  AhB     = smem + BH_BYTES;           // 2 buffers, row stride 48 B
        float* bias_sh = (float*)(smem + BH_BYTES + 2*AH_BYTES);

        // weights -> fp16 in smem: Bh[d][k]  (ONCE per block)
        for (int t = tid; t < 128*CBc; t += 256) {
            int d = t / CBc, k = t - d*CBc;
            float w = (d < 64) ? Wk1[d*CBc + k] : Wk2[(d-64)*CBc + k];
            *(__half*)(BhB + d*176 + k*2) = __float2half(w);
        }
        if (tid < 128) bias_sh[tid] = (tid < 64) ? bk1[tid] : bk2[tid-64];

        int pxl   = tid & 127;        // loader: pixel column
        int khalf = tid >> 7;         // loader: k-octet (0/1)
        int lane = tid & 31, warp = tid >> 5;
        int r4 = lane >> 2, tg = lane & 3;
        int wm = warp & 3, wn = warp >> 2;     // wm: 32-px group, wn: 64-d half

        for (int tile = blockIdx.x; tile < KM_TILES; tile += KM_PERSIST) {
            int m0   = tile * 128;
            int bn   = m0 / HW;
            int pix0 = m0 - bn*HW;
            const float* Abase = img + (size_t)bn*CBc*HW + pix0;

            // prefetch chunk 0 into registers (overlaps prior epilogue/sync)
            float f[8];
            {
                const float* ls = Abase + (size_t)(khalf*8)*HW + pxl;
                #pragma unroll
                for (int j = 0; j < 8; j++) f[j] = ls[(size_t)j*HW];
            }
            __syncthreads();   // prior tile's readers done with buf 0 (covers Bh fill on iter 0)
            {
                uint4 u;
                u.x = h2u(__floats2half2_rn(f[0], f[1]));
                u.y = h2u(__floats2half2_rn(f[2], f[3]));
                u.z = h2u(__floats2half2_rn(f[4], f[5]));
                u.w = h2u(__floats2half2_rn(f[6], f[7]));
                *(uint4*)(AhB + pxl*48 + khalf*16) = u;
            }
            __syncthreads();

            float acc[2][8][4];
            #pragma unroll
            for (int mf = 0; mf < 2; mf++)
                #pragma unroll
                for (int nf = 0; nf < 8; nf++)
                    #pragma unroll
                    for (int i = 0; i < 4; i++) acc[mf][nf][i] = 0.f;

            #pragma unroll
            for (int kc = 0; kc < 5; kc++) {       // K = 80 = 5 x 16
                if (kc < 4) {                      // prefetch next chunk (LDG only)
                    const float* ls = Abase + (size_t)((kc+1)*16 + khalf*8)*HW + pxl;
                    #pragma unroll
                    for (int j = 0; j < 8; j++) f[j] = ls[(size_t)j*HW];
                }

                const char* A = AhB + (kc & 1)*AH_BYTES;
                // load BOTH A fragment sets first, then stream B once
                uint32_t a[2][4];
                #pragma unroll
                for (int mf = 0; mf < 2; mf++) {
                    const char* ar = A + (wm*32 + mf*16 + r4)*48 + tg*4;
                    a[mf][0] = *(const uint32_t*)(ar);
                    a[mf][1] = *(const uint32_t*)(ar + 8*48);
                    a[mf][2] = *(const uint32_t*)(ar + 16);
                    a[mf][3] = *(const uint32_t*)(ar + 8*48 + 16);
                }
                #pragma unroll
                for (int nf = 0; nf < 8; nf++) {
                    const char* br = BhB + (wn*64 + nf*8 + r4)*176 + kc*32 + tg*4;
                    uint32_t b0 = *(const uint32_t*)(br);
                    uint32_t b1 = *(const uint32_t*)(br + 16);
                    mma_f16(acc[0][nf], a[0][0], a[0][1], a[0][2], a[0][3], b0, b1);
                    mma_f16(acc[1][nf], a[1][0], a[1][1], a[1][2], a[1][3], b0, b1);
                }

                if (kc < 4) {                      // store next chunk, then sync
                    uint4 u;
                    u.x = h2u(__floats2half2_rn(f[0], f[1]));
                    u.y = h2u(__floats2half2_rn(f[2], f[3]));
                    u.z = h2u(__floats2half2_rn(f[4], f[5]));
                    u.w = h2u(__floats2half2_rn(f[6], f[7]));
                    *(uint4*)(AhB + ((kc+1)&1)*AH_BYTES + pxl*48 + khalf*16) = u;
                    __syncthreads();
                }
            }

            // epilogue: bias + fp16 interleaved store
            #pragma unroll
            for (int nf = 0; nf < 8; nf++) {
                int dl   = wn*64 + nf*8 + 2*tg;
                float b0 = bias_sh[dl], b1 = bias_sh[dl+1];
                int widx = (wn == 0) ? dl : (dl - 63);  // half2 word in record
                #pragma unroll
                for (int mf = 0; mf < 2; mf++) {
                    int px = m0 + wm*32 + mf*16 + r4;
                    g_KMIh[(size_t)px*64 + widx] =
                        __floats2half2_rn(acc[mf][nf][0]+b0, acc[mf][nf][1]+b1);
                    g_KMIh[(size_t)(px+8)*64 + widx] =
                        __floats2half2_rn(acc[mf][nf][2]+b0, acc[mf][nf][3]+b1);
                }
            }
        }
        return;
    }

    if (blockIdx.x < KM_PERSIST + QG_BLOCKS) {
        // ================= q-GEMM path (fp32 cores) =================
        float* BshT    = dyn;                    // [64][132]
        float* Ash2    = BshT + 64*132;          // [8][132]
        float* bias_sh = Ash2 + 8*132;           // [128]

        {
            int d  = tid >> 1;
            const float* src = (d < 64) ? &Wq1[d*64] : &Wq2[(d-64)*64];
            #pragma unroll
            for (int i = 0; i < 8; i++) {
                int k = (tid & 1)*4 + 8*i;
                float4 w = *(const float4*)&src[k];
                BshT[(k+0)*132 + d] = w.x; BshT[(k+1)*132 + d] = w.y;
                BshT[(k+2)*132 + d] = w.z; BshT[(k+3)*132 + d] = w.w;
            }
        }
        if (tid < 128) bias_sh[tid] = (tid < 64) ? bq1[tid] : bq2[tid-64];

        int p0 = (blockIdx.x - KM_PERSIST) * 128;
        int tx = tid & 15, ty = tid >> 4;

        float acc[8][8];
        #pragma unroll
        for (int i = 0; i < 8; i++)
            #pragma unroll
            for (int j = 0; j < 8; j++) acc[i][j] = 0.f;

        #pragma unroll
        for (int kc = 0; kc < 8; kc++) {
            __syncthreads();
            {
                int px = tid >> 1;
                int k0 = (tid & 1)*4;
                float4 a = *(const float4*)&vox[(size_t)(p0+px)*64 + kc*8 + k0];
                Ash2[(k0+0)*132 + px] = a.x; Ash2[(k0+1)*132 + px] = a.y;
                Ash2[(k0+2)*132 + px] = a.z; Ash2[(k0+3)*132 + px] = a.w;
            }
            __syncthreads();
            #pragma unroll
            for (int k = 0; k < 8; k++) {
                float4 a0 = *(const float4*)&Ash2[k*132 + ty*4];
                float4 a1 = *(const float4*)&Ash2[k*132 + 64 + ty*4];
                float4 b0 = *(const float4*)&BshT[(kc*8+k)*132 + tx*4];
                float4 b1 = *(const float4*)&BshT[(kc*8+k)*132 + 64 + tx*4];
                float av[8] = {a0.x,a0.y,a0.z,a0.w, a1.x,a1.y,a1.z,a1.w};
                float bv[8] = {b0.x,b0.y,b0.z,b0.w, b1.x,b1.y,b1.z,b1.w};
                #pragma unroll
                for (int i = 0; i < 8; i++)
                    #pragma unroll
                    for (int j = 0; j < 8; j++)
                        acc[i][j] += av[i] * bv[j];
            }
        }

        float bj1[4], bj2[4];
        #pragma unroll
        for (int j = 0; j < 4; j++) {
            bj1[j] = bias_sh[tx*4 + j];
            bj2[j] = bias_sh[64 + tx*4 + j];
        }
        #pragma unroll
        for (int i = 0; i < 8; i++) {
            int p = p0 + ((i < 4) ? (ty*4 + i) : (64 + ty*4 + (i - 4)));
            float4 o1 = make_float4(acc[i][0]+bj1[0], acc[i][1]+bj1[1],
                                    acc[i][2]+bj1[2], acc[i][3]+bj1[3]);
            float4 o2 = make_float4(acc[i][4]+bj2[0], acc[i][5]+bj2[1],
                                    acc[i][6]+bj2[2], acc[i][7]+bj2[3]);
            *(float4*)&g_Q[(size_t)p*128 + tx*4]      = o1;
            *(float4*)&g_Q[(size_t)p*128 + 64 + tx*4] = o2;
        }
        return;
    }

    // ================= compaction path =================
    {
        int cb   = blockIdx.x - KM_PERSIST - QG_BLOCKS;
        int p    = cb * 256 + tid;
        int lane = tid & 31;

        bool sel = (p < Pp) && (cmask[p] > 1);
        unsigned mask = __ballot_sync(0xffffffffu, sel);

        int wbase = 0;
        if (lane == 0) wbase = atomicAdd(&g_selcnt, __popc(mask));
        wbase = __shfl_sync(0xffffffffu, wbase, 0);
        if (sel)
            g_selidx[wbase + __popc(mask & ((1u << lane) - 1u))] = p;

        int rowbase = cb * 256 + (tid >> 5) * 32;
        #pragma unroll 4
        for (int j = 0; j < 32; j++) {
            int pj = rowbase + j;
            if (pj < Pp && !((mask >> j) & 1u)) {
                float2 t = *(const float2*)&vox[(size_t)pj*64 + 2*lane];
                *(float2*)&out[(size_t)pj*64 + 2*lane] = t;
            }
        }
    }
}

// ---------------------------------------------------------------------------
// Kernel 2: fused attention over DENSE sel list. 4 points per warp,
// rcp.approx projection, no-max softmax with zero-denominator guard.
// ---------------------------------------------------------------------------
__global__ __launch_bounds__(256, 4) void attn_fused_kernel(
    const float* __restrict__ vox,
    const int*   __restrict__ coords,
    const float* __restrict__ proj,
    const float* __restrict__ origins,
    const float* __restrict__ Wq2,
    float* __restrict__ out)
{
    __shared__ float WqT2[64][64];        // WqT2[i][d] = Wq2[d][i]
    __shared__ float projs[Bc*Nv*12];
    __shared__ float orig_s[Bc*3];

    int cnt = g_selcnt;
    if (blockIdx.x * 32 >= cnt) return;   // block-uniform early exit

    int tid = threadIdx.x;
    for (int t = tid; t < 1024; t += 256) {
        int d = t >> 4, i0 = (t & 15) * 4;
        float4 w = *(const float4*)&Wq2[d*64 + i0];
        WqT2[i0+0][d] = w.x; WqT2[i0+1][d] = w.y;
        WqT2[i0+2][d] = w.z; WqT2[i0+3][d] = w.w;
    }
    if (tid < Bc*Nv*12) projs[tid] = proj[tid];
    if (tid < Bc*3)     orig_s[tid] = origins[tid];
    __syncthreads();

    int warp = tid >> 5, lane = tid & 31;

    #pragma unroll 1
    for (int c = 0; c < 4; c++) {
        int widx = blockIdx.x * 32 + c * 8 + warp;
        if (widx >= cnt) break;           // warp-uniform
        int p = g_selidx[widx];

        float2 v   = *(const float2*)&vox[(size_t)p*64 + 2*lane];
        float2 q1  = *(const float2*)&g_Q[(size_t)p*128 + 2*lane];
        float2 q2v = *(const float2*)&g_Q[(size_t)p*128 + 64 + 2*lane];

        int4 cc = __ldg((const int4*)coords + p);
        int bi = cc.w;
        float X = (float)cc.x * 0.16f + orig_s[bi*3 + 0];
        float Y = (float)cc.y * 0.16f + orig_s[bi*3 + 1];
        float Z = (float)cc.z * 0.16f + orig_s[bi*3 + 2];

        float2 k1s[9], k2s[9];
        unsigned mbits = 0;

        // Phase A: gather all views
        #pragma unroll
        for (int n = 0; n < Nv; n++) {
            const float* Pm = &projs[(bi*Nv + n)*12];
            float c0 = Pm[0]*X + Pm[1]*Y + Pm[2]*Z  + Pm[3];
            float c1 = Pm[4]*X + Pm[5]*Y + Pm[6]*Z  + Pm[7];
            float c2 = Pm[8]*X + Pm[9]*Y + Pm[10]*Z + Pm[11];
            float inv = frcp(c2);
            float txp = c0 * inv;
            float typ = c1 * inv;
            bool msk = (c2 > 0.0f) &&
                       (txp >= 0.0f) && (txp <= (float)(Ww-1)) &&
                       (typ >= 0.0f) && (typ <= (float)(Hh-1));
            float px = msk ? txp : 0.0f;
            float py = msk ? typ : 0.0f;

            float x0f = floorf(px), y0f = floorf(py);
            float fx = px - x0f,    fy = py - y0f;
            int x0 = (int)x0f, y0 = (int)y0f;
            bool vx1 = (x0 + 1) < Ww;
            bool vy1 = (y0 + 1) < Hh;
            int x1 = vx1 ? x0 + 1 : x0;
            int y1r = vy1 ? y0 + 1 : y0;
            float mskf = msk ? 1.f : 0.f;
            float w00 = (1.f-fx)*(1.f-fy) * mskf;
            float w01 = (vx1 ? fx*(1.f-fy) : 0.f) * mskf;
            float w10 = (vy1 ? (1.f-fx)*fy : 0.f) * mskf;
            float w11 = ((vx1 && vy1) ? fx*fy : 0.f) * mskf;

            const __half2* rb = g_KMIh + ((size_t)(bi*Nv + n)*HW)*64 + 2*lane;
            uint2 u00 = *(const uint2*)(rb + (size_t)(y0 *Ww + x0)*64);
            uint2 u01 = *(const uint2*)(rb + (size_t)(y0 *Ww + x1)*64);
            uint2 u10 = *(const uint2*)(rb + (size_t)(y1r*Ww + x0)*64);
            uint2 u11 = *(const uint2*)(rb + (size_t)(y1r*Ww + x1)*64);

            float2 a00 = __half22float2(*(__half2*)&u00.x);
            float2 b00 = __half22float2(*(__half2*)&u00.y);
            float2 a01 = __half22float2(*(__half2*)&u01.x);
            float2 b01 = __half22float2(*(__half2*)&u01.y);
            float2 a10 = __half22float2(*(__half2*)&u10.x);
            float2 b10 = __half22float2(*(__half2*)&u10.y);
            float2 a11 = __half22float2(*(__half2*)&u11.x);
            float2 b11 = __half22float2(*(__half2*)&u11.y);

            k1s[n].x = w00*a00.x + w01*a01.x + w10*a10.x + w11*a11.x;
            k1s[n].y = w00*a00.y + w01*a01.y + w10*a10.y + w11*a11.y;
            k2s[n].x = w00*b00.x + w01*b01.x + w10*b10.x + w11*b11.x;
            k2s[n].y = w00*b00.y + w01*b01.y + w10*b10.y + w11*b11.y;
            mbits |= (msk ? 1u : 0u) << n;
        }

        // Phase B: batched block-1 logit reductions
        float pt[9];
        #pragma unroll
        for (int n = 0; n < Nv; n++)
            pt[n] = q1.x*k1s[n].x + q1.y*k1s[n].y;
        #pragma unroll
        for (int off = 16; off; off >>= 1)
            #pragma unroll
            for (int n = 0; n < Nv; n++)
                pt[n] += __shfl_xor_sync(0xffffffffu, pt[n], off);

        // softmax 1 (no max-sub: logits bounded; masked -> exactly 0;
        // empty-mask guard: inv = 0 when se == 0)
        float se = 0.f;
        float2 y1 = make_float2(0.f, 0.f);
        #pragma unroll
        for (int n = 0; n < Nv; n++) {
            float e = ((mbits >> n) & 1u) ? __expf(pt[n]*0.125f) : 0.f;
            se += e;
            y1.x += e*k1s[n].x;
            y1.y += e*k1s[n].y;
        }
        float inv1 = (se > 0.f) ? __fdiv_rn(1.0f, se) : 0.f;
        float2 yn = make_float2(y1.x*inv1, y1.y*inv1);
        float2 f1 = make_float2(v.x + yn.x, v.y + yn.y);

        // q2 = q2v + Wq2 @ yn  (4-way split accumulators)
        float2 d0 = make_float2(0.f,0.f), d1 = d0, d2 = d0, d3 = d0;
        #pragma unroll
        for (int s = 0; s < 16; s++) {
            float aX = __shfl_sync(0xffffffffu, yn.x, s);
            float aY = __shfl_sync(0xffffffffu, yn.y, s);
            float bX = __shfl_sync(0xffffffffu, yn.x, s + 16);
            float bY = __shfl_sync(0xffffffffu, yn.y, s + 16);
            float2 wa0 = *(const float2*)&WqT2[2*s][2*lane];
            float2 wa1 = *(const float2*)&WqT2[2*s+1][2*lane];
            float2 wb0 = *(const float2*)&WqT2[2*s+32][2*lane];
            float2 wb1 = *(const float2*)&WqT2[2*s+33][2*lane];
            d0.x += wa0.x*aX; d0.y += wa0.y*aX;
            d1.x += wa1.x*aY; d1.y += wa1.y*aY;
            d2.x += wb0.x*bX; d2.y += wb0.y*bX;
            d3.x += wb1.x*bY; d3.y += wb1.y*bY;
        }
        float2 q2;
        q2.x = q2v.x + (d0.x + d1.x) + (d2.x + d3.x);
        q2.y = q2v.y + (d0.y + d1.y) + (d2.y + d3.y);

        // Phase D: batched block-2 logits + softmax
        #pragma unroll
        for (int n = 0; n < Nv; n++)
            pt[n] = q2.x*k2s[n].x + q2.y*k2s[n].y;
        #pragma unroll
        for (int off = 16; off; off >>= 1)
            #pragma unroll
            for (int n = 0; n < Nv; n++)
                pt[n] += __shfl_xor_sync(0xffffffffu, pt[n], off);
        float se2 = 0.f;
        float2 y2 = make_float2(0.f, 0.f);
        #pragma unroll
        for (int n = 0; n < Nv; n++) {
            float e = ((mbits >> n) & 1u) ? __expf(pt[n]*0.125f) : 0.f;
            se2 += e;
            y2.x += e*k2s[n].x;
            y2.y += e*k2s[n].y;
        }
        float inv2 = (se2 > 0.f) ? __fdiv_rn(1.0f, se2) : 0.f;
        float2 o;
        o.x = f1.x + y2.x*inv2;
        o.y = f1.y + y2.y*inv2;
        *(float2*)&out[(size_t)p*64 + 2*lane] = o;
    }
}

// ---------------------------------------------------------------------------
extern "C" void kernel_launch(void* const* d_in, const int* in_sizes, int n_in,
                              void* d_out, int out_size)
{
    (void)in_sizes; (void)n_in; (void)out_size;
    const float* img    = (const float*)d_in[0];
    const int*   coords = (const int*)  d_in[1];
    const float* vox    = (const float*)d_in[2];
    const float* proj   = (const float*)d_in[3];
    const float* orig   = (const float*)d_in[4];
    const int*   cmask  = (const int*)  d_in[5];
    const float* Wq1 = (const float*)d_in[6];
    const float* bq1 = (const float*)d_in[7];
    const float* Wk1 = (const float*)d_in[8];
    const float* bk1 = (const float*)d_in[9];
    const float* Wq2 = (const float*)d_in[10];
    const float* bq2 = (const float*)d_in[11];
    const float* Wk2 = (const float*)d_in[12];
    const float* bk2 = (const float*)d_in[13];
    float* out = (float*)d_out;

    const int KQ_SMEM = (KM_SMEM > QG_SMEM) ? KM_SMEM : QG_SMEM;  // 38528
    static int smem_set = 0;
    if (!smem_set) {
        cudaFuncSetAttribute(keymap_qgemm_kernel,
                             cudaFuncAttributeMaxDynamicSharedMemorySize, KQ_SMEM);
        smem_set = 1;
    }

    void* cntp = nullptr;
    cudaGetSymbolAddress(&cntp, g_selcnt);
    cudaMemsetAsync(cntp, 0, sizeof(int));

    keymap_qgemm_kernel<<<KM_PERSIST + QG_BLOCKS + CP_BLOCKS, 256, KQ_SMEM>>>(
        img, Wk1, bk1, Wk2, bk2, vox, Wq1, bq1, Wq2, bq2, cmask, out);
    attn_fused_kernel<<<AT_BLOCKS, 256>>>(vox, coords, proj, orig, Wq2, out);
}